// round 13
// baseline (speedup 1.0000x reference)
#include <cuda_runtime.h>
#include <cstdint>

#define TRACKS   512
#define FEATURES 256
#define ROW_ELEMS 262145            // 1 + 512*512
#define BULK      262144            // 512*512 elements per row after the leading score

// np.float32(math.log(1e-46))
__device__ __constant__ float MASK_VAL = -105.91891427772612f;

// Cross-kernel scratch (device globals: allocation-free, allowed)
__device__ float g_scores[TRACKS];
__device__ int   g_idx;

// ---------------------------------------------------------------------------
// Prologue (single block, 512 threads): thread t computes dot(x[t], W) + b,
// then a shared-memory tree argmax with first-occurrence tie-break.
// One kernel node replaces memset + scores + argmax. W is staged in smem
// (broadcast reads), x rows are read per-thread (all bytes consumed, L1-hot).
// ---------------------------------------------------------------------------
__global__ void __launch_bounds__(512) prologue_kernel(const float* __restrict__ x,
                                                       const float* __restrict__ W,
                                                       const float* __restrict__ b) {
    __shared__ float  sW[FEATURES];
    __shared__ float  sv[TRACKS];
    __shared__ int    si[TRACKS];
    const int t = threadIdx.x;

    if (t < FEATURES) sW[t] = W[t];
    __syncthreads();

    const float4* xr = reinterpret_cast<const float4*>(x + (size_t)t * FEATURES);
    const float4* wr = reinterpret_cast<const float4*>(sW);

    float s = 0.0f;
    #pragma unroll
    for (int i = 0; i < FEATURES / 4; i++) {
        float4 a = xr[i];
        float4 w = wr[i];           // warp-broadcast smem read
        s += a.x * w.x + a.y * w.y + a.z * w.z + a.w * w.w;
    }
    s += b[0];

    g_scores[t] = s;
    sv[t] = s;
    si[t] = t;
    __syncthreads();

    #pragma unroll
    for (int off = TRACKS / 2; off; off >>= 1) {
        if (t < off) {
            float v2 = sv[t + off];
            int   i2 = si[t + off];
            if (v2 > sv[t] || (v2 == sv[t] && i2 < si[t])) {
                sv[t] = v2;
                si[t] = i2;
            }
        }
        __syncthreads();
    }
    if (t == 0) g_idx = si[0];
}

// ---------------------------------------------------------------------------
// Fill: streaming write of the (512, 262145) output.
// Row r: out[r][0] = s; out[r][1 + j] = ((j & 511) == idx) ? s*MASK : s.
// The grid stride (32 blocks * 256 thr * 4 elems = 32768) is a multiple of
// the 512-element mask period, so each thread's column phase is loop-
// invariant: value computed once, the loop is a pure STG.128 stream.
// Plain stores (NOT __stcs): tail stores left dirty in L2 flush during the
// next replay's DRAM-idle prologue — free overlap in the graph loop.
// Rows are mutually misaligned (stride 262145 floats), so a tiny scalar
// prologue/epilogue brackets the aligned float4 bulk.
// ---------------------------------------------------------------------------
__global__ void __launch_bounds__(256) fill_kernel(float* __restrict__ out) {
    const int r = blockIdx.y;
    const float s = g_scores[r];
    const int idx = g_idx;
    const float sm = s * MASK_VAL;

    float* p = out + (size_t)r * ROW_ELEMS;

    // p+1 is offset (r*262145 + 1) floats from out; alignment phase = (r+1) & 3
    const int a = (4 - ((r + 1) & 3)) & 3;        // scalar prologue elements
    const int e = (4 - a) & 3;                    // scalar epilogue elements
    const int N4 = (BULK - a - e) >> 2;           // aligned float4 count

    if (blockIdx.x == 0) {
        int t = threadIdx.x;
        if (t == 0) p[0] = s;
        if (t >= 1 && t <= a) {
            int j = t - 1;                        // j < 3 < 512
            p[1 + j] = (j == idx) ? sm : s;
        }
        if (t >= 4 && t < 4 + e) {
            int j = BULK - e + (t - 4);
            p[1 + j] = ((j & 511) == idx) ? sm : s;
        }
    }

    float4* q4 = reinterpret_cast<float4*>(p + 1 + a);
    const int tid    = blockIdx.x * blockDim.x + threadIdx.x;   // < 8192
    const int stride = gridDim.x * blockDim.x;                  // 8192 float4

    // Column phase is constant across the grid-stride loop (stride*4 % 512 == 0)
    const int c = (a + (tid << 2)) & 511;
    float4 v;
    v.x = (c               == idx) ? sm : s;
    v.y = (((c + 1) & 511) == idx) ? sm : s;
    v.z = (((c + 2) & 511) == idx) ? sm : s;
    v.w = (((c + 3) & 511) == idx) ? sm : s;

    #pragma unroll 4
    for (int t = tid; t < N4; t += stride)
        q4[t] = v;
}

// ---------------------------------------------------------------------------
// Launch: fused prologue -> fill (2 graph nodes total)
// ---------------------------------------------------------------------------
extern "C" void kernel_launch(void* const* d_in, const int* in_sizes, int n_in,
                              void* d_out, int out_size) {
    const float* x = (const float*)d_in[0];   // (512, 256)
    const float* W = (const float*)d_in[1];   // (1, 256)
    const float* b = (const float*)d_in[2];   // (1,)
    float* out = (float*)d_out;               // (512, 262145)

    prologue_kernel<<<1, TRACKS>>>(x, W, b);

    dim3 grid(32, TRACKS);
    fill_kernel<<<grid, 256>>>(out);
}

// round 14
// speedup vs baseline: 1.0049x; 1.0049x over previous
#include <cuda_runtime.h>
#include <cstdint>

#define TRACKS   512
#define FEATURES 256
#define ROW_ELEMS 262145            // 1 + 512*512
#define BULK      262144            // 512*512 elements per row after the leading score

// np.float32(math.log(1e-46))
__device__ __constant__ float MASK_VAL = -105.91891427772612f;

// Cross-kernel scratch (device globals: allocation-free, allowed)
__device__ float g_scores[TRACKS];
__device__ int   g_idx;

// ---------------------------------------------------------------------------
// Prologue (single block, 512 threads): thread t computes dot(x[t], W) + b,
// then a shared-memory tree argmax with first-occurrence tie-break.
// One kernel node replaces memset + scores + argmax. W is staged in smem
// (broadcast reads), x rows are read per-thread (all bytes consumed, L1-hot).
// ---------------------------------------------------------------------------
__global__ void __launch_bounds__(512) prologue_kernel(const float* __restrict__ x,
                                                       const float* __restrict__ W,
                                                       const float* __restrict__ b) {
    __shared__ float  sW[FEATURES];
    __shared__ float  sv[TRACKS];
    __shared__ int    si[TRACKS];
    const int t = threadIdx.x;

    if (t < FEATURES) sW[t] = W[t];
    __syncthreads();

    const float4* xr = reinterpret_cast<const float4*>(x + (size_t)t * FEATURES);
    const float4* wr = reinterpret_cast<const float4*>(sW);

    float s = 0.0f;
    #pragma unroll
    for (int i = 0; i < FEATURES / 4; i++) {
        float4 a = xr[i];
        float4 w = wr[i];           // warp-broadcast smem read
        s += a.x * w.x + a.y * w.y + a.z * w.z + a.w * w.w;
    }
    s += b[0];

    g_scores[t] = s;
    sv[t] = s;
    si[t] = t;
    __syncthreads();

    #pragma unroll
    for (int off = TRACKS / 2; off; off >>= 1) {
        if (t < off) {
            float v2 = sv[t + off];
            int   i2 = si[t + off];
            if (v2 > sv[t] || (v2 == sv[t] && i2 < si[t])) {
                sv[t] = v2;
                si[t] = i2;
            }
        }
        __syncthreads();
    }
    if (t == 0) g_idx = si[0];
}

// ---------------------------------------------------------------------------
// Fill: streaming write of the (512, 262145) output.
// Row r: out[r][0] = s; out[r][1 + j] = ((j & 511) == idx) ? s*MASK : s.
// The grid stride (32 blocks * 256 thr * 4 elems = 32768) is a multiple of
// the 512-element mask period, so each thread's column phase is loop-
// invariant: value computed once, the loop is a pure STG.128 stream.
// Plain stores (NOT __stcs): tail stores left dirty in L2 flush during the
// next replay's DRAM-idle prologue — free overlap in the graph loop.
// Rows are mutually misaligned (stride 262145 floats), so a tiny scalar
// prologue/epilogue brackets the aligned float4 bulk.
// ---------------------------------------------------------------------------
__global__ void __launch_bounds__(256) fill_kernel(float* __restrict__ out) {
    const int r = blockIdx.y;
    const float s = g_scores[r];
    const int idx = g_idx;
    const float sm = s * MASK_VAL;

    float* p = out + (size_t)r * ROW_ELEMS;

    // p+1 is offset (r*262145 + 1) floats from out; alignment phase = (r+1) & 3
    const int a = (4 - ((r + 1) & 3)) & 3;        // scalar prologue elements
    const int e = (4 - a) & 3;                    // scalar epilogue elements
    const int N4 = (BULK - a - e) >> 2;           // aligned float4 count

    if (blockIdx.x == 0) {
        int t = threadIdx.x;
        if (t == 0) p[0] = s;
        if (t >= 1 && t <= a) {
            int j = t - 1;                        // j < 3 < 512
            p[1 + j] = (j == idx) ? sm : s;
        }
        if (t >= 4 && t < 4 + e) {
            int j = BULK - e + (t - 4);
            p[1 + j] = ((j & 511) == idx) ? sm : s;
        }
    }

    float4* q4 = reinterpret_cast<float4*>(p + 1 + a);
    const int tid    = blockIdx.x * blockDim.x + threadIdx.x;   // < 8192
    const int stride = gridDim.x * blockDim.x;                  // 8192 float4

    // Column phase is constant across the grid-stride loop (stride*4 % 512 == 0)
    const int c = (a + (tid << 2)) & 511;
    float4 v;
    v.x = (c               == idx) ? sm : s;
    v.y = (((c + 1) & 511) == idx) ? sm : s;
    v.z = (((c + 2) & 511) == idx) ? sm : s;
    v.w = (((c + 3) & 511) == idx) ? sm : s;

    #pragma unroll 4
    for (int t = tid; t < N4; t += stride)
        q4[t] = v;
}

// ---------------------------------------------------------------------------
// Launch: fused prologue -> fill (2 graph nodes total)
// ---------------------------------------------------------------------------
extern "C" void kernel_launch(void* const* d_in, const int* in_sizes, int n_in,
                              void* d_out, int out_size) {
    const float* x = (const float*)d_in[0];   // (512, 256)
    const float* W = (const float*)d_in[1];   // (1, 256)
    const float* b = (const float*)d_in[2];   // (1,)
    float* out = (float*)d_out;               // (512, 262145)

    prologue_kernel<<<1, TRACKS>>>(x, W, b);

    dim3 grid(32, TRACKS);
    fill_kernel<<<grid, 256>>>(out);
}

// round 15
// speedup vs baseline: 1.0052x; 1.0003x over previous
#include <cuda_runtime.h>
#include <cstdint>

#define TRACKS   512
#define FEATURES 256
#define ROW_ELEMS 262145            // 1 + 512*512
#define BULK      262144            // 512*512 elements per row after the leading score

// np.float32(math.log(1e-46))
__device__ __constant__ float MASK_VAL = -105.91891427772612f;

// Cross-kernel scratch (device globals: allocation-free, allowed)
__device__ float g_scores[TRACKS];
__device__ int   g_idx;

// ---------------------------------------------------------------------------
// Prologue (single block, 512 threads): thread t computes dot(x[t], W) + b,
// then a shared-memory tree argmax with first-occurrence tie-break.
// One kernel node replaces memset + scores + argmax. W is staged in smem
// (broadcast reads), x rows are read per-thread (all bytes consumed, L1-hot).
// ---------------------------------------------------------------------------
__global__ void __launch_bounds__(512) prologue_kernel(const float* __restrict__ x,
                                                       const float* __restrict__ W,
                                                       const float* __restrict__ b) {
    __shared__ float  sW[FEATURES];
    __shared__ float  sv[TRACKS];
    __shared__ int    si[TRACKS];
    const int t = threadIdx.x;

    if (t < FEATURES) sW[t] = W[t];
    __syncthreads();

    const float4* xr = reinterpret_cast<const float4*>(x + (size_t)t * FEATURES);
    const float4* wr = reinterpret_cast<const float4*>(sW);

    float s = 0.0f;
    #pragma unroll
    for (int i = 0; i < FEATURES / 4; i++) {
        float4 a = xr[i];
        float4 w = wr[i];           // warp-broadcast smem read
        s += a.x * w.x + a.y * w.y + a.z * w.z + a.w * w.w;
    }
    s += b[0];

    g_scores[t] = s;
    sv[t] = s;
    si[t] = t;
    __syncthreads();

    #pragma unroll
    for (int off = TRACKS / 2; off; off >>= 1) {
        if (t < off) {
            float v2 = sv[t + off];
            int   i2 = si[t + off];
            if (v2 > sv[t] || (v2 == sv[t] && i2 < si[t])) {
                sv[t] = v2;
                si[t] = i2;
            }
        }
        __syncthreads();
    }
    if (t == 0) g_idx = si[0];
}

// ---------------------------------------------------------------------------
// Fill: streaming write of the (512, 262145) output.
// Row r: out[r][0] = s; out[r][1 + j] = ((j & 511) == idx) ? s*MASK : s.
// The grid stride (32 blocks * 256 thr * 4 elems = 32768) is a multiple of
// the 512-element mask period, so each thread's column phase is loop-
// invariant: value computed once, the loop is a pure STG.128 stream.
// Plain stores (NOT __stcs): tail stores left dirty in L2 flush during the
// next replay's DRAM-idle prologue — free overlap in the graph loop.
// Rows are mutually misaligned (stride 262145 floats), so a tiny scalar
// prologue/epilogue brackets the aligned float4 bulk.
// ---------------------------------------------------------------------------
__global__ void __launch_bounds__(256) fill_kernel(float* __restrict__ out) {
    const int r = blockIdx.y;
    const float s = g_scores[r];
    const int idx = g_idx;
    const float sm = s * MASK_VAL;

    float* p = out + (size_t)r * ROW_ELEMS;

    // p+1 is offset (r*262145 + 1) floats from out; alignment phase = (r+1) & 3
    const int a = (4 - ((r + 1) & 3)) & 3;        // scalar prologue elements
    const int e = (4 - a) & 3;                    // scalar epilogue elements
    const int N4 = (BULK - a - e) >> 2;           // aligned float4 count

    if (blockIdx.x == 0) {
        int t = threadIdx.x;
        if (t == 0) p[0] = s;
        if (t >= 1 && t <= a) {
            int j = t - 1;                        // j < 3 < 512
            p[1 + j] = (j == idx) ? sm : s;
        }
        if (t >= 4 && t < 4 + e) {
            int j = BULK - e + (t - 4);
            p[1 + j] = ((j & 511) == idx) ? sm : s;
        }
    }

    float4* q4 = reinterpret_cast<float4*>(p + 1 + a);
    const int tid    = blockIdx.x * blockDim.x + threadIdx.x;   // < 8192
    const int stride = gridDim.x * blockDim.x;                  // 8192 float4

    // Column phase is constant across the grid-stride loop (stride*4 % 512 == 0)
    const int c = (a + (tid << 2)) & 511;
    float4 v;
    v.x = (c               == idx) ? sm : s;
    v.y = (((c + 1) & 511) == idx) ? sm : s;
    v.z = (((c + 2) & 511) == idx) ? sm : s;
    v.w = (((c + 3) & 511) == idx) ? sm : s;

    #pragma unroll 4
    for (int t = tid; t < N4; t += stride)
        q4[t] = v;
}

// ---------------------------------------------------------------------------
// Launch: fused prologue -> fill (2 graph nodes total)
// ---------------------------------------------------------------------------
extern "C" void kernel_launch(void* const* d_in, const int* in_sizes, int n_in,
                              void* d_out, int out_size) {
    const float* x = (const float*)d_in[0];   // (512, 256)
    const float* W = (const float*)d_in[1];   // (1, 256)
    const float* b = (const float*)d_in[2];   // (1,)
    float* out = (float*)d_out;               // (512, 262145)

    prologue_kernel<<<1, TRACKS>>>(x, W, b);

    dim3 grid(32, TRACKS);
    fill_kernel<<<grid, 256>>>(out);
}

// round 16
// speedup vs baseline: 1.0068x; 1.0016x over previous
#include <cuda_runtime.h>
#include <cstdint>

#define TRACKS   512
#define FEATURES 256
#define ROW_ELEMS 262145            // 1 + 512*512
#define BULK      262144            // 512*512 elements per row after the leading score

// np.float32(math.log(1e-46))
__device__ __constant__ float MASK_VAL = -105.91891427772612f;

// Cross-kernel scratch (device globals: allocation-free, allowed)
__device__ float g_scores[TRACKS];
__device__ int   g_idx;

// ---------------------------------------------------------------------------
// Prologue (single block, 512 threads): thread t computes dot(x[t], W) + b,
// then a shared-memory tree argmax with first-occurrence tie-break.
// One kernel node replaces memset + scores + argmax. W is staged in smem
// (broadcast reads), x rows are read per-thread (all bytes consumed, L1-hot).
// ---------------------------------------------------------------------------
__global__ void __launch_bounds__(512) prologue_kernel(const float* __restrict__ x,
                                                       const float* __restrict__ W,
                                                       const float* __restrict__ b) {
    __shared__ float  sW[FEATURES];
    __shared__ float  sv[TRACKS];
    __shared__ int    si[TRACKS];
    const int t = threadIdx.x;

    if (t < FEATURES) sW[t] = W[t];
    __syncthreads();

    const float4* xr = reinterpret_cast<const float4*>(x + (size_t)t * FEATURES);
    const float4* wr = reinterpret_cast<const float4*>(sW);

    float s = 0.0f;
    #pragma unroll
    for (int i = 0; i < FEATURES / 4; i++) {
        float4 a = xr[i];
        float4 w = wr[i];           // warp-broadcast smem read
        s += a.x * w.x + a.y * w.y + a.z * w.z + a.w * w.w;
    }
    s += b[0];

    g_scores[t] = s;
    sv[t] = s;
    si[t] = t;
    __syncthreads();

    #pragma unroll
    for (int off = TRACKS / 2; off; off >>= 1) {
        if (t < off) {
            float v2 = sv[t + off];
            int   i2 = si[t + off];
            if (v2 > sv[t] || (v2 == sv[t] && i2 < si[t])) {
                sv[t] = v2;
                si[t] = i2;
            }
        }
        __syncthreads();
    }
    if (t == 0) g_idx = si[0];
}

// ---------------------------------------------------------------------------
// Fill: streaming write of the (512, 262145) output.
// Row r: out[r][0] = s; out[r][1 + j] = ((j & 511) == idx) ? s*MASK : s.
// The grid stride (32 blocks * 256 thr * 4 elems = 32768) is a multiple of
// the 512-element mask period, so each thread's column phase is loop-
// invariant: value computed once, the loop is a pure STG.128 stream.
// Plain stores (NOT __stcs): tail stores left dirty in L2 flush during the
// next replay's DRAM-idle prologue — free overlap in the graph loop.
// Rows are mutually misaligned (stride 262145 floats), so a tiny scalar
// prologue/epilogue brackets the aligned float4 bulk.
// ---------------------------------------------------------------------------
__global__ void __launch_bounds__(256) fill_kernel(float* __restrict__ out) {
    const int r = blockIdx.y;
    const float s = g_scores[r];
    const int idx = g_idx;
    const float sm = s * MASK_VAL;

    float* p = out + (size_t)r * ROW_ELEMS;

    // p+1 is offset (r*262145 + 1) floats from out; alignment phase = (r+1) & 3
    const int a = (4 - ((r + 1) & 3)) & 3;        // scalar prologue elements
    const int e = (4 - a) & 3;                    // scalar epilogue elements
    const int N4 = (BULK - a - e) >> 2;           // aligned float4 count

    if (blockIdx.x == 0) {
        int t = threadIdx.x;
        if (t == 0) p[0] = s;
        if (t >= 1 && t <= a) {
            int j = t - 1;                        // j < 3 < 512
            p[1 + j] = (j == idx) ? sm : s;
        }
        if (t >= 4 && t < 4 + e) {
            int j = BULK - e + (t - 4);
            p[1 + j] = ((j & 511) == idx) ? sm : s;
        }
    }

    float4* q4 = reinterpret_cast<float4*>(p + 1 + a);
    const int tid    = blockIdx.x * blockDim.x + threadIdx.x;   // < 8192
    const int stride = gridDim.x * blockDim.x;                  // 8192 float4

    // Column phase is constant across the grid-stride loop (stride*4 % 512 == 0)
    const int c = (a + (tid << 2)) & 511;
    float4 v;
    v.x = (c               == idx) ? sm : s;
    v.y = (((c + 1) & 511) == idx) ? sm : s;
    v.z = (((c + 2) & 511) == idx) ? sm : s;
    v.w = (((c + 3) & 511) == idx) ? sm : s;

    #pragma unroll 4
    for (int t = tid; t < N4; t += stride)
        q4[t] = v;
}

// ---------------------------------------------------------------------------
// Launch: fused prologue -> fill (2 graph nodes total)
// ---------------------------------------------------------------------------
extern "C" void kernel_launch(void* const* d_in, const int* in_sizes, int n_in,
                              void* d_out, int out_size) {
    const float* x = (const float*)d_in[0];   // (512, 256)
    const float* W = (const float*)d_in[1];   // (1, 256)
    const float* b = (const float*)d_in[2];   // (1,)
    float* out = (float*)d_out;               // (512, 262145)

    prologue_kernel<<<1, TRACKS>>>(x, W, b);

    dim3 grid(32, TRACKS);
    fill_kernel<<<grid, 256>>>(out);
}

// round 17
// speedup vs baseline: 1.2447x; 1.2363x over previous
#include <cuda_runtime.h>
#include <cstdint>

#define TRACKS   512
#define FEATURES 256
#define ROW_ELEMS 262145            // 1 + 512*512
#define BULK      262144            // 512*512 elements per row after the leading score
#define CHUNK4    2048              // float4 per fill block (32 blocks/row)

// np.float32(math.log(1e-46))
__device__ __constant__ float MASK_VAL = -105.91891427772612f;

// Cross-kernel scratch (device global: allocation-free, allowed)
__device__ float g_scores[TRACKS];

// Monotone map fp32 -> u32 (order-preserving)
__device__ __forceinline__ unsigned int float_ordered(float f) {
    unsigned int u = __float_as_uint(f);
    return u ^ ((((int)u) >> 31) | 0x80000000u);
}

__device__ __forceinline__ unsigned long long pack_score(float s, int i) {
    // max over packs == (max score, then smallest index) : first-occurrence tie-break
    return ((unsigned long long)float_ordered(s) << 32) |
           (unsigned long long)(0xFFFFFFFFu - (unsigned int)i);
}

// ---------------------------------------------------------------------------
// Kernel A: one warp per row computes dot(x[r], W) + b -> g_scores[r].
// 256 blocks x 64 threads = 512 warps spread across every SM. No atomics,
// no reset node needed.
// ---------------------------------------------------------------------------
__global__ void __launch_bounds__(64) scores_kernel(const float* __restrict__ x,
                                                    const float* __restrict__ W,
                                                    const float* __restrict__ b) {
    int gwarp = (blockIdx.x * blockDim.x + threadIdx.x) >> 5;
    int lane  = threadIdx.x & 31;
    if (gwarp >= TRACKS) return;

    const float4* xr = reinterpret_cast<const float4*>(x + (size_t)gwarp * FEATURES);
    const float4* wr = reinterpret_cast<const float4*>(W);

    // FEATURES/4 = 64 float4 per row; each lane takes [lane] and [lane+32]
    float4 a0 = xr[lane];
    float4 a1 = xr[lane + 32];
    float4 w0 = __ldg(&wr[lane]);
    float4 w1 = __ldg(&wr[lane + 32]);

    float s = a0.x * w0.x + a0.y * w0.y + a0.z * w0.z + a0.w * w0.w
            + a1.x * w1.x + a1.y * w1.y + a1.z * w1.z + a1.w * w1.w;

    #pragma unroll
    for (int off = 16; off; off >>= 1)
        s += __shfl_xor_sync(0xffffffffu, s, off);

    if (lane == 0)
        g_scores[gwarp] = s + b[0];
}

// ---------------------------------------------------------------------------
// Kernel B: streaming fill of the (512, 262145) output.
// Each block first computes the argmax over the 512 scores REDUNDANTLY
// (2 KB, L2-hot, ~hundreds of cycles — cheaper than a separate kernel node),
// then writes its contiguous 32 KB chunk of row r.
//
// Row r: out[r][0] = s; out[r][1 + j] = ((j & 511) == idx) ? s*MASK : s.
// Inner-loop stride is 256 float4 = 1024 elems == 0 (mod 512), so each
// thread's column phase is loop-invariant: value computed once, the loop is
// a pure STG.128 stream over a contiguous region (DRAM-page friendly).
// Rows are mutually misaligned (stride 262145 floats), so a tiny scalar
// prologue/epilogue brackets the aligned float4 bulk.
// ---------------------------------------------------------------------------
__global__ void __launch_bounds__(256) fill_kernel(float* __restrict__ out) {
    __shared__ unsigned long long red[8];
    const int t = threadIdx.x;
    const int r = blockIdx.y;

    // ---- redundant per-block argmax over g_scores (first-occurrence) ----
    unsigned long long p0 = pack_score(g_scores[t],       t);
    unsigned long long p1 = pack_score(g_scores[t + 256], t + 256);
    unsigned long long pk = p0 > p1 ? p0 : p1;
    #pragma unroll
    for (int off = 16; off; off >>= 1) {
        unsigned long long o = __shfl_xor_sync(0xffffffffu, pk, off);
        if (o > pk) pk = o;
    }
    if ((t & 31) == 0) red[t >> 5] = pk;
    __syncthreads();
    if (t == 0) {
        unsigned long long m = red[0];
        #pragma unroll
        for (int w = 1; w < 8; w++) if (red[w] > m) m = red[w];
        red[0] = m;
    }
    __syncthreads();
    const int idx = (int)(0xFFFFFFFFu - (unsigned int)(red[0] & 0xFFFFFFFFull));

    const float s  = g_scores[r];
    const float sm = s * MASK_VAL;

    float* p = out + (size_t)r * ROW_ELEMS;

    // p+1 is offset (r*262145 + 1) floats from out; alignment phase = (r+1) & 3
    const int a  = (4 - ((r + 1) & 3)) & 3;       // scalar prologue elements
    const int e  = (4 - a) & 3;                   // scalar epilogue elements
    const int N4 = (BULK - a - e) >> 2;           // aligned float4 count

    if (blockIdx.x == 0) {
        if (t == 0) p[0] = s;
        if (t >= 1 && t <= a) {
            int j = t - 1;                        // j < 3 < 512
            p[1 + j] = (j == idx) ? sm : s;
        }
        if (t >= 4 && t < 4 + e) {
            int j = BULK - e + (t - 4);
            p[1 + j] = ((j & 511) == idx) ? sm : s;
        }
    }

    float4* q4 = reinterpret_cast<float4*>(p + 1 + a);
    const int base = blockIdx.x * CHUNK4;         // contiguous chunk start
    const int end  = min(base + CHUNK4, N4);

    // Column phase is constant across the inner loop (256*4 % 512 == 0)
    const int c = (a + ((base + t) << 2)) & 511;
    float4 v;
    v.x = (c               == idx) ? sm : s;
    v.y = (((c + 1) & 511) == idx) ? sm : s;
    v.z = (((c + 2) & 511) == idx) ? sm : s;
    v.w = (((c + 3) & 511) == idx) ? sm : s;

    #pragma unroll
    for (int q = 0; q < CHUNK4 / 256; q++) {
        int i = base + q * 256 + t;
        if (i < end) q4[i] = v;
    }
}

// ---------------------------------------------------------------------------
// Launch: scores -> fill (2 graph nodes total)
// ---------------------------------------------------------------------------
extern "C" void kernel_launch(void* const* d_in, const int* in_sizes, int n_in,
                              void* d_out, int out_size) {
    const float* x = (const float*)d_in[0];   // (512, 256)
    const float* W = (const float*)d_in[1];   // (1, 256)
    const float* b = (const float*)d_in[2];   // (1,)
    float* out = (float*)d_out;               // (512, 262145)

    // Scores: 512 warps over 256 blocks (full-chip spread)
    scores_kernel<<<256, 64>>>(x, W, b);

    // Fill: 32 contiguous chunks per row x 512 rows, 256 threads each
    dim3 grid(32, TRACKS);
    fill_kernel<<<grid, 256>>>(out);
}